// round 6
// baseline (speedup 1.0000x reference)
#include <cuda_runtime.h>
#include <cstdint>

#define BB 32
#define TT 350
#define NIN 2312
#define NHID 500
#define MP12 512
#define MP3 64
#define NWT 11          // ceil(350/32)
#define NCOLS (BB*TT)   // 11200
#define NCP 11264       // NCOLS padded to 128
#define THETA 10.0f
#define LMAX 32
#define KMAX 128

// ------------------ static scratch ------------------
__device__ unsigned g_xmask[(size_t)NIN*BB*NWT];
__device__ unsigned g_m1  [(size_t)MP12*BB*NWT];
__device__ float    g_psp [(size_t)NIN*NCP];        // reused for hidden psp (rows < 512)
__device__ float    g_h   [(size_t)NCP*MP12];       // drive, layout (col, o)
__device__ float    g_h3  [(size_t)NCP*MP3];

// ------------------ pack spikes into per-(i,b) t-bitmasks ------------------
__global__ void pack_x_kernel(const float* __restrict__ x) {
    const int i = blockIdx.x*32 + threadIdx.y;
    const int t = blockIdx.y*32 + threadIdx.x;
    const int b = blockIdx.z;
    float v = 0.f;
    if (i < NIN && t < TT) v = x[((size_t)b*NIN + i)*TT + t];
    const unsigned m = __ballot_sync(0xffffffffu, v != 0.0f);
    if (threadIdx.x == 0 && i < NIN)
        g_xmask[((size_t)i*BB + b)*NWT + blockIdx.y] = m;
}

// ------------------ causal conv over t, fp64 accumulation (true value), f32 output ----
__global__ void __launch_bounds__(128) conv_sparse(
    const unsigned* __restrict__ mask, float* __restrict__ psp,
    const float* __restrict__ srm, int K, int nrows) {
    __shared__ double srm_s[KMAX];
    __shared__ unsigned short evs[4][352];
    for (int j = threadIdx.x; j < K; j += blockDim.x) srm_s[j] = (double)srm[j];
    __syncthreads();
    const int wid = threadIdx.x >> 5, lane = threadIdx.x & 31;
    const int row = blockIdx.x*4 + wid;
    if (row >= nrows) return;
    unsigned w = (lane < NWT) ? mask[(size_t)row*NWT + lane] : 0u;
    int c = __popc(w);
    int inc = c;
    for (int d = 1; d < 32; d <<= 1) {
        int v = __shfl_up_sync(0xffffffffu, inc, d);
        if (lane >= d) inc += v;
    }
    const int excl = inc - c;
    const int total = __shfl_sync(0xffffffffu, inc, 31);
    unsigned mm = w; int p = excl;
    while (mm) {
        int bp = __ffs(mm) - 1; mm &= mm - 1;
        evs[wid][p++] = (unsigned short)(lane*32 + bp);
    }
    __syncwarp();
    const int k = row / BB, b = row % BB;
    float* op = psp + (size_t)k*NCP + (size_t)b*TT;
    for (int c2 = 0; c2 < NWT; ++c2) {
        const int t = c2*32 + lane;
        if (t >= TT) break;
        double acc = 0.0;
        for (int e = 0; e < total; ++e) {
            const int te = evs[wid][e];
            if (te > t) break;
            const int j = t - te;
            if (j < K) acc += srm_s[j];
        }
        op[t] = (float)acc;
    }
}

// ------------------ GEMM with fp64 accumulation: C[col][o] = sum_k A[o][k]*B[k][col] ----
__global__ void __launch_bounds__(256) gemm_d(
    const float* __restrict__ A, const float* __restrict__ B, float* __restrict__ C,
    int M, int Ka, int MPo) {
    __shared__ float As[8][68];
    __shared__ float Bs[8][68];
    const int tid = threadIdx.x;
    const int tx = tid & 15, ty = tid >> 4;
    const int n0 = blockIdx.x*64, m0 = blockIdx.y*64;
    double acc[4][4];
#pragma unroll
    for (int i = 0; i < 4; ++i)
#pragma unroll
        for (int j = 0; j < 4; ++j) acc[i][j] = 0.0;
    const int nkt = (Ka + 7) >> 3;
    for (int kt = 0; kt < nkt; ++kt) {
        const int k0 = kt*8;
        {
            const int r = tid & 63;          // o within tile
            const int kh = tid >> 6;         // 0..3
#pragma unroll
            for (int q = 0; q < 2; ++q) {
                const int k = k0 + kh*2 + q;
                const int m = m0 + r;
                As[kh*2+q][r] = (m < M && k < Ka) ? A[(size_t)m*Ka + k] : 0.f;
            }
        }
        if (tid < 128) {
            const int kk = tid >> 4;         // 0..7
            const int nq = (tid & 15)*4;     // 0..60
            const int k = k0 + kk;
            float4 v = make_float4(0.f,0.f,0.f,0.f);
            if (k < Ka) v = *(const float4*)&B[(size_t)k*NCP + n0 + nq];
            Bs[kk][nq+0]=v.x; Bs[kk][nq+1]=v.y; Bs[kk][nq+2]=v.z; Bs[kk][nq+3]=v.w;
        }
        __syncthreads();
#pragma unroll
        for (int kk = 0; kk < 8; ++kk) {
            double a[4], bq[4];
#pragma unroll
            for (int i = 0; i < 4; ++i) a[i]  = (double)As[kk][ty*4 + i];
#pragma unroll
            for (int j = 0; j < 4; ++j) bq[j] = (double)Bs[kk][tx*4 + j];
#pragma unroll
            for (int i = 0; i < 4; ++i)
#pragma unroll
                for (int j = 0; j < 4; ++j)
                    acc[i][j] = fma(a[i], bq[j], acc[i][j]);
        }
        __syncthreads();
    }
#pragma unroll
    for (int j = 0; j < 4; ++j) {
        const int col = n0 + tx*4 + j;
#pragma unroll
        for (int i = 0; i < 4; ++i) {
            const int o = m0 + ty*4 + i;
            if (o < MPo) C[(size_t)col*MPo + o] = (float)acc[i][j];
        }
    }
}

// ------------------ layer-3 skinny GEMM, fp64 accumulation ------------------
__global__ void __launch_bounds__(128) gemm3_f64(
    const float* __restrict__ W3, const float* __restrict__ psp, float* __restrict__ C) {
    const int col = blockIdx.x*128 + threadIdx.x;
    const int o = blockIdx.y;
    const float* wp = W3 + (size_t)o*NHID;
    const float* bp = psp + col;
    double acc = 0.0;
    for (int k = 0; k < NHID; ++k)
        acc = fma((double)wp[k], (double)bp[(size_t)k*NCP], acc);
    C[(size_t)col*MP3 + o] = (float)acc;
}

// ------------------ sequential refractory spike layer (literal reference scan, f32) ----
template<int OW, bool WMASK, bool WOUT>
__global__ void __launch_bounds__(OW) spike_k(
    const float* __restrict__ h, unsigned* __restrict__ mask, float* __restrict__ out,
    const float* __restrict__ ref, int L, int MPo) {
    __shared__ float tile[32][OW];
    const int b = blockIdx.y;
    const int o = blockIdx.x*OW + threadIdx.x;
    float rf[LMAX], rb[LMAX];
#pragma unroll
    for (int j = 0; j < LMAX; ++j) { rf[j] = (j < L) ? ref[j] : 0.f; rb[j] = 0.f; }
    unsigned curw = 0;
    for (int ch = 0; ch < NWT; ++ch) {
        const int tcnt = (TT - ch*32 < 32) ? (TT - ch*32) : 32;
        __syncthreads();
        for (int r = 0; r < tcnt; ++r)
            tile[r][threadIdx.x] = h[((size_t)b*TT + ch*32 + r)*MPo + o];
        __syncthreads();
        for (int r = 0; r < tcnt; ++r) {
            const int t = ch*32 + r;
            const float u = tile[r][threadIdx.x] + rb[0];
            const bool s = (u >= THETA);
            if (s) {
#pragma unroll
                for (int j = 1; j < LMAX; ++j) rb[j] += rf[j];
                curw |= (1u << (t & 31));
            }
            // unconditional shift, exactly as the reference scan does
#pragma unroll
            for (int j = 0; j < LMAX-1; ++j) rb[j] = rb[j+1];
            rb[LMAX-1] = 0.f;
            if (WOUT && o < 10) out[((size_t)b*10 + o)*TT + t] = s ? 1.f : 0.f;
        }
        if (WMASK) { mask[((size_t)o*BB + b)*NWT + ch] = curw; curw = 0; }
    }
}

extern "C" void kernel_launch(void* const* d_in, const int* in_sizes, int n_in,
                              void* d_out, int out_size) {
    const float* x   = (const float*)d_in[0];
    const float* W1  = (const float*)d_in[1];
    const float* W2  = (const float*)d_in[2];
    const float* W3  = (const float*)d_in[3];
    const float* srm = (const float*)d_in[4];
    const float* ref = (const float*)d_in[5];
    int K = in_sizes[4]; if (K > KMAX) K = KMAX;
    int L = in_sizes[5]; if (L > LMAX) L = LMAX;
    float* out = (float*)d_out;

    void *pxm, *pm1, *ppsp, *ph, *ph3;
    cudaGetSymbolAddress(&pxm,  g_xmask);
    cudaGetSymbolAddress(&pm1,  g_m1);
    cudaGetSymbolAddress(&ppsp, g_psp);
    cudaGetSymbolAddress(&ph,   g_h);
    cudaGetSymbolAddress(&ph3,  g_h3);

    // layer 1: conv(x) -> W1 -> spike
    pack_x_kernel<<<dim3((NIN+31)/32, NWT, BB), dim3(32,32)>>>(x);
    conv_sparse<<<(NIN*BB + 3)/4, 128>>>((const unsigned*)pxm, (float*)ppsp, srm, K, NIN*BB);
    gemm_d<<<dim3(NCP/64, MP12/64), 256>>>(W1, (const float*)ppsp, (float*)ph, NHID, NIN, MP12);
    spike_k<128, true, false><<<dim3(MP12/128, BB), 128>>>(
        (const float*)ph, (unsigned*)pm1, nullptr, ref, L, MP12);

    // layer 2
    conv_sparse<<<(NHID*BB + 3)/4, 128>>>((const unsigned*)pm1, (float*)ppsp, srm, K, NHID*BB);
    gemm_d<<<dim3(NCP/64, MP12/64), 256>>>(W2, (const float*)ppsp, (float*)ph, NHID, NHID, MP12);
    spike_k<128, true, false><<<dim3(MP12/128, BB), 128>>>(
        (const float*)ph, (unsigned*)pm1, nullptr, ref, L, MP12);

    // layer 3
    conv_sparse<<<(NHID*BB + 3)/4, 128>>>((const unsigned*)pm1, (float*)ppsp, srm, K, NHID*BB);
    gemm3_f64<<<dim3(NCP/128, 10), 128>>>(W3, (const float*)ppsp, (float*)ph3);
    spike_k<64, false, true><<<dim3(1, BB), 64>>>(
        (const float*)ph3, nullptr, out, ref, L, MP3);
}

// round 9
// speedup vs baseline: 4.7724x; 4.7724x over previous
#include <cuda_runtime.h>
#include <cstdint>

#define BB 32
#define TT 350
#define NIN 2312
#define NHID 500
#define MP12 512
#define MP3 32
#define NW1C 73         // ceil(2312/32) words per column (layer-1 input bits)
#define NW2C 16         // 512/32 words per column (hidden bits)
#define NWT 11          // ceil(350/32)
#define NINPAD (NW1C*32)
#define NCOLS (BB*TT)   // 11200
#define THETA 10.0f
#define LMAX 32
#define KMAX 128
#define CONVR 25        // t-tile (350 = 14*25)

// ------------------ static scratch ------------------
__device__ unsigned g_cm1[(size_t)NCOLS*NW1C];
__device__ unsigned g_cm2[(size_t)NCOLS*NW2C];
__device__ float    g_W1T[(size_t)NINPAD*MP12];
__device__ float    g_W2T[(size_t)MP12*MP12];
__device__ float    g_W3T[(size_t)MP12*MP3];
__device__ double   g_Gd [(size_t)NCOLS*MP12];
__device__ double   g_G3 [(size_t)NCOLS*MP3];
__device__ float    g_h  [(size_t)NCOLS*MP12];
__device__ float    g_h3 [(size_t)NCOLS*MP3];

// ------------------ pack x into per-(b,t) i-bitmasks ------------------
__global__ void pack_x_kernel(const float* __restrict__ x) {
    __shared__ float tile[32][33];
    const int ib = blockIdx.x, tb = blockIdx.y, b = blockIdx.z;
    const int i = ib*32 + threadIdx.y;
    const int t = tb*32 + threadIdx.x;
    float v = 0.f;
    if (i < NIN && t < TT) v = x[((size_t)b*NIN + i)*TT + t];
    tile[threadIdx.y][threadIdx.x] = v;
    __syncthreads();
    const int tt = tb*32 + threadIdx.y;   // lanes (threadIdx.x) now index i-bits
    const float w = tile[threadIdx.x][threadIdx.y];
    const unsigned m = __ballot_sync(0xffffffffu, w != 0.0f);
    if (threadIdx.x == 0 && tt < TT)
        g_cm1[(size_t)(b*TT + tt)*NW1C + ib] = m;
}

// ------------------ transpose W (O x I) into padded WT (Ipad x Opad) ------------------
__global__ void transpose_pad(const float* __restrict__ W, float* __restrict__ WT,
                              int rows, int cols, int opad, int ipad) {
    __shared__ float tile[32][33];
    const int i0 = blockIdx.x*32, o0 = blockIdx.y*32;
    const int i = i0 + threadIdx.x, o = o0 + threadIdx.y;
    float v = 0.f;
    if (o < rows && i < cols) v = W[(size_t)o*cols + i];
    tile[threadIdx.y][threadIdx.x] = v;
    __syncthreads();
    const int oo = o0 + threadIdx.x, ii = i0 + threadIdx.y;
    if (ii < ipad && oo < opad)
        WT[(size_t)ii*opad + oo] = tile[threadIdx.x][threadIdx.y];
}

// ------------------ sparse GEMM (fp64 acc): G[col][o] = sum_{i in events(col)} WT[i][o] ----
// Event extraction by warp 0 with a deterministic warp-scan (ascending word order).
__global__ void __launch_bounds__(256) gemm_sp(
    const unsigned* __restrict__ cm, const float* __restrict__ WT,
    double* __restrict__ Gd, int nw) {
    __shared__ unsigned short evs[768];
    __shared__ int cnt;
    const int col = blockIdx.x;
    const int tid = threadIdx.x;
    if (tid < 32) {
        const int lane = tid;
        int base = 0;
        for (int w0 = 0; w0 < nw; w0 += 32) {
            const int w = w0 + lane;
            unsigned m = (w < nw) ? cm[(size_t)col*nw + w] : 0u;
            int c = __popc(m);
            int inc = c;
#pragma unroll
            for (int d = 1; d < 32; d <<= 1) {
                int v = __shfl_up_sync(0xffffffffu, inc, d);
                if (lane >= d) inc += v;
            }
            int p = base + inc - c;
            while (m) {
                int bp = __ffs(m) - 1; m &= m - 1;
                evs[p++] = (unsigned short)(w*32 + bp);
            }
            base += __shfl_sync(0xffffffffu, inc, 31);
        }
        if (lane == 0) cnt = base;
    }
    __syncthreads();
    const int n = cnt;
    double a0 = 0.0, a1 = 0.0;
    for (int e = 0; e < n; ++e) {
        const int i = evs[e];
        a0 += (double)WT[(size_t)i*MP12 + tid];
        a1 += (double)WT[(size_t)i*MP12 + 256 + tid];
    }
    Gd[(size_t)col*MP12 + tid] = a0;
    Gd[(size_t)col*MP12 + 256 + tid] = a1;
}

// ------------------ layer-3 sparse GEMM: warp per column, 32-wide outputs ----
__global__ void __launch_bounds__(128) gemm_sp3(
    const unsigned* __restrict__ cm, const float* __restrict__ WT,
    double* __restrict__ G3) {
    const int wid = threadIdx.x >> 5, lane = threadIdx.x & 31;
    const int col = blockIdx.x*4 + wid;
    double a = 0.0;
    for (int w = 0; w < NW2C; ++w) {
        unsigned m = cm[(size_t)col*NW2C + w];
        while (m) {
            int bp = __ffs(m) - 1; m &= m - 1;
            a += (double)WT[(size_t)(w*32 + bp)*MP3 + lane];
        }
    }
    G3[(size_t)col*MP3 + lane] = a;
}

// ------------------ dense causal conv over t on fp64 G, f32 drive out ----
template<int OW>
__global__ void __launch_bounds__(OW) conv_d(
    const double* __restrict__ Gd, float* __restrict__ h,
    const float* __restrict__ srm, int K, int MPo) {
    __shared__ double srm_s[KMAX];
    for (int j = threadIdx.x; j < K; j += OW) srm_s[j] = (double)srm[j];
    __syncthreads();
    const int o = blockIdx.y*OW + threadIdx.x;
    const int t0 = blockIdx.x*CONVR;
    const int b = blockIdx.z;
    const double* Gb = Gd + (size_t)(b*TT)*MPo + o;
    double acc[CONVR];
#pragma unroll
    for (int r = 0; r < CONVR; ++r) acc[r] = 0.0;
    int mlo = t0 - (K-1); if (mlo < 0) mlo = 0;
    int mhi = t0 + CONVR - 1; if (mhi > TT-1) mhi = TT-1;
    int m = mlo;
    int aEnd = t0 - K + CONVR - 1; if (aEnd > mhi) aEnd = mhi;
    for (; m <= aEnd; ++m) {            // top edge: j may exceed K-1
        const double v = Gb[(size_t)m*MPo];
        const int d = t0 - m;
#pragma unroll
        for (int r = 0; r < CONVR; ++r) { const int j = d + r; if (j < K) acc[r] += srm_s[j]*v; }
    }
    int bEnd = (t0 < mhi) ? t0 : mhi;
    for (; m <= bEnd; ++m) {            // interior: full window, no predicates
        const double v = Gb[(size_t)m*MPo];
        const int d = t0 - m;
#pragma unroll
        for (int r = 0; r < CONVR; ++r) acc[r] += srm_s[d + r]*v;
    }
    for (; m <= mhi; ++m) {             // bottom edge: j may be negative
        const double v = Gb[(size_t)m*MPo];
        const int d = t0 - m;
#pragma unroll
        for (int r = 0; r < CONVR; ++r) {
            const int j = d + r;
            const int jc = (j < 0) ? 0 : j;
            if (j >= 0) acc[r] += srm_s[jc]*v;
        }
    }
#pragma unroll
    for (int r = 0; r < CONVR; ++r) {
        const int t = t0 + r;
        if (t < TT) h[((size_t)b*TT + t)*MPo + o] = (float)acc[r];
    }
}

// ------------------ sequential refractory spike layer (literal reference scan, f32) ----
template<int OW, bool WMASK, bool WOUT>
__global__ void __launch_bounds__(OW) spike_k(
    const float* __restrict__ h, unsigned* __restrict__ maskcol, float* __restrict__ out,
    const float* __restrict__ ref, int L, int MPo) {
    __shared__ float tile[32][OW];
    const int b = blockIdx.y;
    const int o = blockIdx.x*OW + threadIdx.x;
    const int wid = threadIdx.x >> 5, lane = threadIdx.x & 31;
    const int gw = blockIdx.x*(OW/32) + wid;   // global o-word index
    float rf[LMAX], rb[LMAX];
#pragma unroll
    for (int j = 0; j < LMAX; ++j) { rf[j] = (j < L) ? ref[j] : 0.f; rb[j] = 0.f; }
    for (int ch = 0; ch < NWT; ++ch) {
        const int tcnt = (TT - ch*32 < 32) ? (TT - ch*32) : 32;
        __syncthreads();
        for (int r = 0; r < tcnt; ++r)
            tile[r][threadIdx.x] = h[((size_t)b*TT + ch*32 + r)*MPo + o];
        __syncthreads();
        for (int r = 0; r < tcnt; ++r) {
            const int t = ch*32 + r;
            const float u = tile[r][threadIdx.x] + rb[0];
            const bool s = (u >= THETA);
            const unsigned m = __ballot_sync(0xffffffffu, s);
            if (s) {
#pragma unroll
                for (int j = 1; j < LMAX; ++j) rb[j] += rf[j];
            }
#pragma unroll
            for (int j = 0; j < LMAX-1; ++j) rb[j] = rb[j+1];
            rb[LMAX-1] = 0.f;
            if (WMASK && lane == 0) maskcol[(size_t)(b*TT + t)*NW2C + gw] = m;
            if (WOUT && o < 10) out[((size_t)b*10 + o)*TT + t] = s ? 1.f : 0.f;
        }
    }
}

extern "C" void kernel_launch(void* const* d_in, const int* in_sizes, int n_in,
                              void* d_out, int out_size) {
    const float* x   = (const float*)d_in[0];
    const float* W1  = (const float*)d_in[1];
    const float* W2  = (const float*)d_in[2];
    const float* W3  = (const float*)d_in[3];
    const float* srm = (const float*)d_in[4];
    const float* ref = (const float*)d_in[5];
    int K = in_sizes[4]; if (K > KMAX) K = KMAX;
    int L = in_sizes[5]; if (L > LMAX) L = LMAX;
    float* out = (float*)d_out;

    void *pcm1, *pcm2, *pw1, *pw2, *pw3, *pgd, *pg3, *ph, *ph3;
    cudaGetSymbolAddress(&pcm1, g_cm1);
    cudaGetSymbolAddress(&pcm2, g_cm2);
    cudaGetSymbolAddress(&pw1,  g_W1T);
    cudaGetSymbolAddress(&pw2,  g_W2T);
    cudaGetSymbolAddress(&pw3,  g_W3T);
    cudaGetSymbolAddress(&pgd,  g_Gd);
    cudaGetSymbolAddress(&pg3,  g_G3);
    cudaGetSymbolAddress(&ph,   g_h);
    cudaGetSymbolAddress(&ph3,  g_h3);

    // weights transpose + pad
    transpose_pad<<<dim3(NW1C, MP12/32), dim3(32,32)>>>(W1, (float*)pw1, NHID, NIN, MP12, NINPAD);
    transpose_pad<<<dim3(MP12/32, MP12/32), dim3(32,32)>>>(W2, (float*)pw2, NHID, NHID, MP12, MP12);
    transpose_pad<<<dim3(MP12/32, 1), dim3(32,32)>>>(W3, (float*)pw3, 10, NHID, MP3, MP12);

    // layer 1: sparse GEMM(spikes) -> conv -> spike
    pack_x_kernel<<<dim3(NW1C, NWT, BB), dim3(32,32)>>>(x);
    gemm_sp<<<NCOLS, 256>>>((const unsigned*)pcm1, (const float*)pw1, (double*)pgd, NW1C);
    conv_d<128><<<dim3(TT/CONVR, MP12/128, BB), 128>>>((const double*)pgd, (float*)ph, srm, K, MP12);
    spike_k<128, true, false><<<dim3(MP12/128, BB), 128>>>(
        (const float*)ph, (unsigned*)pcm2, nullptr, ref, L, MP12);

    // layer 2
    gemm_sp<<<NCOLS, 256>>>((const unsigned*)pcm2, (const float*)pw2, (double*)pgd, NW2C);
    conv_d<128><<<dim3(TT/CONVR, MP12/128, BB), 128>>>((const double*)pgd, (float*)ph, srm, K, MP12);
    spike_k<128, true, false><<<dim3(MP12/128, BB), 128>>>(
        (const float*)ph, (unsigned*)pcm2, nullptr, ref, L, MP12);

    // layer 3
    gemm_sp3<<<NCOLS/4, 128>>>((const unsigned*)pcm2, (const float*)pw3, (double*)pg3);
    conv_d<32><<<dim3(TT/CONVR, 1, BB), 32>>>((const double*)pg3, (float*)ph3, srm, K, MP3);
    spike_k<32, false, true><<<dim3(1, BB), 32>>>(
        (const float*)ph3, nullptr, out, ref, L, MP3);
}